// round 1
// baseline (speedup 1.0000x reference)
#include <cuda_runtime.h>

// SoftVQLayer: B=4, L=2048, D=1024, V=32, K=4096
#define BLn 8192
#define Dn 1024
#define Vn 32
#define Kn 4096
#define QSZ (BLn*Dn)

// Scratch (device globals; no allocation allowed)
__device__ __align__(16) float g_embnT[Vn*Kn];   // normalized codebook, [v][k]
__device__ __align__(16) float g_hp[BLn*Vn];     // normalized projections, [t][v]
__device__ __align__(16) float g_wpit[Vn*Dn];    // Wpi transposed, [v][d]
__device__ float4 g_wptb[(Dn/4)*Vn];             // Wp blocked: [d4][v] = Wp[v][4d4..4d4+3]

// ---------------- prep: normalize codebook rows -> transposed layout -------
__global__ void k_prep_emb(const float* __restrict__ emb) {
    int w = (blockIdx.x*blockDim.x + threadIdx.x) >> 5;   // code row 0..4095
    int lane = threadIdx.x & 31;                          // v
    float v = emb[w*Vn + lane];
    float s = v*v;
    #pragma unroll
    for (int o = 16; o; o >>= 1) s += __shfl_xor_sync(0xffffffffu, s, o);
    g_embnT[lane*Kn + w] = v * rsqrtf(s);
}

// ---------------- prep: transpose Wpi and block-transpose Wp ---------------
__global__ void k_prep_w(const float* __restrict__ Wp, const float* __restrict__ Wpi,
                         float* __restrict__ out, int out_size) {
    int i = blockIdx.x*blockDim.x + threadIdx.x;          // 0..32767
    int v = i >> 10, d = i & (Dn-1);
    g_wpit[i] = Wpi[d*Vn + v];                            // [v][d] <- [d][v]
    if (i < (Dn/4)*Vn) {
        int d4 = i >> 5, vv = i & 31;
        g_wptb[i] = ((const float4*)Wp)[vv*(Dn/4) + d4];  // [d4][v]
    }
    if (i == 0 && out_size >= QSZ + BLn + 1) out[QSZ + BLn] = 0.0f;  // vq_loss
}

// ---------------- hp = normalize(h @ Wp^T + bp) ----------------------------
// 128 threads (4 warps), warp handles 8 tokens, lane = v.
__global__ __launch_bounds__(128) void k_hp(const float* __restrict__ h,
                                            const float* __restrict__ bp) {
    int wid = threadIdx.x >> 5, lane = threadIdx.x & 31;
    int t0 = (blockIdx.x*4 + wid)*8;
    float acc[8];
    #pragma unroll
    for (int i = 0; i < 8; i++) acc[i] = 0.f;
    #pragma unroll 2
    for (int d4 = 0; d4 < Dn/4; d4++) {
        float4 w = g_wptb[d4*Vn + lane];                  // coalesced
        #pragma unroll
        for (int i = 0; i < 8; i++) {
            float4 a = *(const float4*)(h + (size_t)(t0+i)*Dn + d4*4);  // broadcast
            acc[i] = fmaf(w.x,a.x, fmaf(w.y,a.y, fmaf(w.z,a.z, fmaf(w.w,a.w, acc[i]))));
        }
    }
    float bpv = bp[lane];
    #pragma unroll
    for (int i = 0; i < 8; i++) {
        float x = acc[i] + bpv;
        float s = x*x;
        #pragma unroll
        for (int o = 16; o; o >>= 1) s += __shfl_xor_sync(0xffffffffu, s, o);
        g_hp[(t0+i)*Vn + lane] = x * rsqrtf(s);
    }
}

// ---------------- main: scores -> softmax -> aggregate -> project ----------
// 256 threads, 32 tokens/block. Warp w owns tokens [4w, 4w+4).
__global__ __launch_bounds__(256) void k_main(const float* __restrict__ attn_mask,
        const float* __restrict__ bpi, float* __restrict__ out, int out_size) {
    __shared__ __align__(16) float hpT[Vn][36];      // [v][t]
    __shared__ __align__(16) float embcT[Vn][132];   // chunk, [v][k] padded
    __shared__ __align__(16) float Ps[32][132];      // exp(2s), [t][k] padded
    __shared__ float denom[32];
    __shared__ float vmax[32];
    __shared__ int   vidx[32];
    __shared__ float hvq[32][33];

    int tx = threadIdx.x;
    int wid = tx >> 5, lane = tx & 31;
    int t_base = blockIdx.x * 32;
    int t0 = wid * 4;

    for (int i = tx; i < 32*Vn; i += 256)
        hpT[i & 31][i >> 5] = g_hp[(t_base + (i >> 5))*Vn + (i & 31)];
    if (tx < 32) { denom[tx] = 0.f; vmax[tx] = -3.0e38f; vidx[tx] = 0; }

    float hv0 = 0.f, hv1 = 0.f, hv2 = 0.f, hv3 = 0.f;

    for (int c = 0; c < Kn/128; c++) {
        int kb = c*128;
        __syncthreads();
        // stage codebook chunk: coalesced gmem float4, conflict-free STS
        #pragma unroll
        for (int i4 = tx; i4 < 32*32; i4 += 256) {
            int v = i4 >> 5, k4 = i4 & 31;
            *(float4*)&embcT[v][k4*4] = *(const float4*)(g_embnT + v*Kn + kb + k4*4);
        }
        __syncthreads();

        // GEMM1: s[4 tok][4 codes], codes = lane*4 .. lane*4+3
        float s[4][4];
        #pragma unroll
        for (int i = 0; i < 4; i++)
            #pragma unroll
            for (int j = 0; j < 4; j++) s[i][j] = 0.f;
        #pragma unroll 8
        for (int v = 0; v < Vn; v++) {
            float4 hb = *(const float4*)&hpT[v][t0];         // broadcast
            float4 eb = *(const float4*)&embcT[v][lane*4];   // conflict-free
            float hbv[4] = {hb.x, hb.y, hb.z, hb.w};
            float ebv[4] = {eb.x, eb.y, eb.z, eb.w};
            #pragma unroll
            for (int i = 0; i < 4; i++)
                #pragma unroll
                for (int j = 0; j < 4; j++)
                    s[i][j] = fmaf(hbv[i], ebv[j], s[i][j]);
        }

        // exp + per-token denom / argmax (warp owns its 4 tokens exclusively)
        #pragma unroll
        for (int i = 0; i < 4; i++) {
            float4 e4;
            e4.x = __expf(2.f*s[i][0]); e4.y = __expf(2.f*s[i][1]);
            e4.z = __expf(2.f*s[i][2]); e4.w = __expf(2.f*s[i][3]);
            *(float4*)&Ps[t0+i][lane*4] = e4;
            float es = (e4.x + e4.y) + (e4.z + e4.w);
            float m = s[i][0]; int mk = 0;
            if (s[i][1] > m) { m = s[i][1]; mk = 1; }
            if (s[i][2] > m) { m = s[i][2]; mk = 2; }
            if (s[i][3] > m) { m = s[i][3]; mk = 3; }
            int gk = kb + lane*4 + mk;
            #pragma unroll
            for (int o = 16; o; o >>= 1) {
                es += __shfl_xor_sync(0xffffffffu, es, o);
                float om = __shfl_xor_sync(0xffffffffu, m, o);
                int   ok = __shfl_xor_sync(0xffffffffu, gk, o);
                if (om > m || (om == m && ok < gk)) { m = om; gk = ok; }
            }
            if (lane == 0) {
                denom[t0+i] += es;
                if (m > vmax[t0+i] || (m == vmax[t0+i] && gk < vidx[t0+i])) {
                    vmax[t0+i] = m; vidx[t0+i] = gk;
                }
            }
        }
        __syncthreads();

        // GEMM2: hvq[t][lane] += sum_k Ps[t][k] * embn[k][lane]
        #pragma unroll 4
        for (int kk = 0; kk < 128; kk += 4) {
            float4 ev = *(const float4*)&embcT[lane][kk];     // conflict-free 4-phase
            float4 p0 = *(const float4*)&Ps[t0+0][kk];        // broadcasts
            float4 p1 = *(const float4*)&Ps[t0+1][kk];
            float4 p2 = *(const float4*)&Ps[t0+2][kk];
            float4 p3 = *(const float4*)&Ps[t0+3][kk];
            hv0 = fmaf(p0.x,ev.x, fmaf(p0.y,ev.y, fmaf(p0.z,ev.z, fmaf(p0.w,ev.w, hv0))));
            hv1 = fmaf(p1.x,ev.x, fmaf(p1.y,ev.y, fmaf(p1.z,ev.z, fmaf(p1.w,ev.w, hv1))));
            hv2 = fmaf(p2.x,ev.x, fmaf(p2.y,ev.y, fmaf(p2.z,ev.z, fmaf(p2.w,ev.w, hv2))));
            hv3 = fmaf(p3.x,ev.x, fmaf(p3.y,ev.y, fmaf(p3.z,ev.z, fmaf(p3.w,ev.w, hv3))));
        }
    }
    __syncthreads();

    // finalize: softmax divide + mask + code output
    {
        float hvv[4] = {hv0, hv1, hv2, hv3};
        #pragma unroll
        for (int i = 0; i < 4; i++) {
            int tok = t_base + t0 + i;
            bool on = (attn_mask[tok] == 1.0f);
            float val = on ? hvv[i] / denom[t0+i] : 0.f;
            hvq[t0+i][lane] = val;
            if (lane == 0 && out_size >= QSZ + BLn)
                out[QSZ + tok] = on ? (float)vidx[t0+i] : 0.f;
        }
    }
    __syncthreads();

    // projection: out[t][d] = bpi[d] + sum_v hvq[t][v] * WpiT[v][d]
    if (out_size >= QSZ) {
        float4 bp4 = ((const float4*)bpi)[tx];                // d = tx*4
        for (int tg = 0; tg < 4; tg++) {
            float4 a[8];
            #pragma unroll
            for (int i = 0; i < 8; i++) a[i] = bp4;
            #pragma unroll 4
            for (int v = 0; v < Vn; v++) {
                float4 w = *(const float4*)(g_wpit + v*Dn + tx*4);  // coalesced, L1-hit
                #pragma unroll
                for (int i = 0; i < 8; i++) {
                    float b = hvq[tg*8 + i][v];                     // broadcast
                    a[i].x = fmaf(b, w.x, a[i].x);
                    a[i].y = fmaf(b, w.y, a[i].y);
                    a[i].z = fmaf(b, w.z, a[i].z);
                    a[i].w = fmaf(b, w.w, a[i].w);
                }
            }
            #pragma unroll
            for (int i = 0; i < 8; i++)
                *(float4*)(out + (size_t)(t_base + tg*8 + i)*Dn + tx*4) = a[i];
        }
    }
}

extern "C" void kernel_launch(void* const* d_in, const int* in_sizes, int n_in,
                              void* d_out, int out_size) {
    const float* h         = (const float*)d_in[0];
    const float* attn_mask = (const float*)d_in[1];
    const float* Wp        = (const float*)d_in[2];
    const float* bp        = (const float*)d_in[3];
    const float* Wpi       = (const float*)d_in[4];
    const float* bpi       = (const float*)d_in[5];
    const float* emb       = (const float*)d_in[6];
    float* out = (float*)d_out;

    k_prep_emb<<<Kn/8, 256>>>(emb);                 // 512 blocks, warp per code row
    k_prep_w<<<(Vn*Dn)/256, 256>>>(Wp, Wpi, out, out_size);
    k_hp<<<BLn/32, 128>>>(h, bp);                   // 256 blocks
    k_main<<<BLn/32, 256>>>(attn_mask, bpi, out, out_size);  // 256 blocks
}

// round 3
// speedup vs baseline: 1.4091x; 1.4091x over previous
#include <cuda_runtime.h>

// SoftVQLayer: B=4, L=2048, D=1024, V=32, K=4096
#define BLn 8192
#define Dn 1024
#define Vn 32
#define Kn 4096
#define QSZ (BLn*Dn)

// Scratch (device globals; allocation is forbidden)
__device__ __align__(16) float g_embnT[Vn*Kn];   // normalized codebook, [v][k]
__device__ __align__(16) float g_wpit[Vn*Dn];    // Wpi transposed, [v][d]
__device__ float4 g_wptb[(Dn/4)*Vn];             // Wp blocked: [d4][v]

__device__ __forceinline__ void barg(int id) {
    asm volatile("bar.sync %0, %1;" :: "r"(id), "r"(128) : "memory");
}

// ---------------- prep: normalize codebook rows -> [v][k] -------------------
__global__ void k_prep_emb(const float* __restrict__ emb) {
    int w = (blockIdx.x*blockDim.x + threadIdx.x) >> 5;   // code 0..4095
    int lane = threadIdx.x & 31;                          // v
    float v = emb[w*Vn + lane];
    float s = v*v;
    #pragma unroll
    for (int o = 16; o; o >>= 1) s += __shfl_xor_sync(0xffffffffu, s, o);
    g_embnT[lane*Kn + w] = v * rsqrtf(s);
}

// ---------------- prep: transpose Wpi, block-transpose Wp -------------------
__global__ void k_prep_w(const float* __restrict__ Wp, const float* __restrict__ Wpi,
                         float* __restrict__ out, int out_size) {
    int i = blockIdx.x*blockDim.x + threadIdx.x;          // 0..32767
    int v = i >> 10, d = i & (Dn-1);
    g_wpit[i] = Wpi[d*Vn + v];
    if (i < (Dn/4)*Vn) {
        int d4 = i >> 5, vv = i & 31;
        g_wptb[i] = ((const float4*)Wp)[vv*(Dn/4) + d4];
    }
    if (i == 0 && out_size >= QSZ + BLn + 1) out[QSZ + BLn] = 0.0f;  // vq_loss
}

// ---------------- fused: hp -> scores -> softmax -> aggregate -> project ----
// 256 threads, 32 tokens/block, 256 blocks.
// Warp w: token octet (w&3)*8..+8 ; k-group g=w>>2 handles chunks c with c&1==g.
__global__ __launch_bounds__(256, 3) void k_fused(
    const float* __restrict__ h, const float* __restrict__ bp,
    const float* __restrict__ attn_mask, const float* __restrict__ bpi,
    float* __restrict__ out, int out_size)
{
    // pooled smem with aliasing:
    //  [0,1152)      hpT    [v*36 + t]
    //  [1152,5888)   embk   [(g*64+k)*37 + v]        (alias: hvqP [t'*33+v])
    //  [5888,10240)  Ps     [(w*8+i)*68 + k]         (alias: hstage [t*132+d], hvq [t*33+v])
    __shared__ __align__(16) float sp[10240];
    __shared__ float denomW[8][8];
    __shared__ float maxW[8][8];
    __shared__ int   idxW[8][8];
    __shared__ float denom_s[32];
    __shared__ float mask_s[32];

    float* hpT    = sp;
    float* embk   = sp + 1152;
    float* Ps     = sp + 5888;
    float* hstage = Ps;
    float* hvq    = Ps;
    float* hvqP   = embk;

    int tx = threadIdx.x;
    int wid = tx >> 5, lane = tx & 31;
    int t_base = blockIdx.x * 32;

    // ================= Phase A: hp = normalize(h @ Wp^T + bp) ==============
    {
        int wt4 = wid * 4;                    // warp owns tokens wt4..wt4+3
        float a0 = 0.f, a1 = 0.f, a2 = 0.f, a3 = 0.f;
        for (int c8 = 0; c8 < 8; c8++) {      // 8 chunks of 128 d
            __syncthreads();
            #pragma unroll
            for (int it = 0; it < 4; it++) {
                int i = tx + it*256;
                int t = i >> 5, d4l = i & 31;
                *(float4*)&hstage[t*132 + d4l*4] =
                    *(const float4*)(h + (size_t)(t_base+t)*Dn + c8*128 + d4l*4);
            }
            __syncthreads();
            #pragma unroll 4
            for (int d4l = 0; d4l < 32; d4l++) {
                float4 w4 = g_wptb[(c8*32 + d4l)*32 + lane];
                float4 x0 = *(const float4*)&hstage[(wt4+0)*132 + d4l*4];
                float4 x1 = *(const float4*)&hstage[(wt4+1)*132 + d4l*4];
                float4 x2 = *(const float4*)&hstage[(wt4+2)*132 + d4l*4];
                float4 x3 = *(const float4*)&hstage[(wt4+3)*132 + d4l*4];
                a0 = fmaf(w4.x,x0.x, fmaf(w4.y,x0.y, fmaf(w4.z,x0.z, fmaf(w4.w,x0.w, a0))));
                a1 = fmaf(w4.x,x1.x, fmaf(w4.y,x1.y, fmaf(w4.z,x1.z, fmaf(w4.w,x1.w, a1))));
                a2 = fmaf(w4.x,x2.x, fmaf(w4.y,x2.y, fmaf(w4.z,x2.z, fmaf(w4.w,x2.w, a2))));
                a3 = fmaf(w4.x,x3.x, fmaf(w4.y,x3.y, fmaf(w4.z,x3.z, fmaf(w4.w,x3.w, a3))));
            }
        }
        float bpv = bp[lane];
        float aa[4] = {a0+bpv, a1+bpv, a2+bpv, a3+bpv};
        #pragma unroll
        for (int i = 0; i < 4; i++) {
            float x = aa[i];
            float ss = x*x;
            #pragma unroll
            for (int o = 16; o; o >>= 1) ss += __shfl_xor_sync(0xffffffffu, ss, o);
            hpT[lane*36 + wt4 + i] = x * rsqrtf(ss);   // [v][t]
        }
        __syncthreads();
    }

    // ================= Phase B: scores / softmax / aggregate ================
    int g  = wid >> 2;                    // k-group
    int t0 = (wid & 3) * 8;               // token octet base
    int tg_tid = (wid & 3)*32 + lane;     // tid within group (0..127)
    float* embg = embk + g*(64*37);
    float* Pw   = Ps + (wid*8)*68;

    float es[8], mx[8], hv[8]; int mi[8];
    #pragma unroll
    for (int i = 0; i < 8; i++) { es[i]=0.f; mx[i]=-3.0e38f; mi[i]=0; hv[i]=0.f; }

    for (int cc = 0; cc < 32; cc++) {
        int kb = (cc*2 + g) * 64;
        barg(1+g);                        // group done reading prev chunk
        #pragma unroll
        for (int it = 0; it < 16; it++) { // stage 64 codes x 32 v, [k][v] pad 37
            int i = tg_tid + it*128;
            int kl = i & 63, v = i >> 6;
            embg[kl*37 + v] = g_embnT[v*Kn + kb + kl];
        }
        barg(1+g);

        // GEMM1: s[8 tok][2 codes], codes = lane, lane+32 (conflict-free: stride 37)
        float s0[8], s1[8];
        #pragma unroll
        for (int i = 0; i < 8; i++) { s0[i] = 0.f; s1[i] = 0.f; }
        #pragma unroll 2
        for (int v = 0; v < 32; v++) {
            float4 h0 = *(const float4*)&hpT[v*36 + t0];      // broadcast
            float4 h1 = *(const float4*)&hpT[v*36 + t0 + 4];  // broadcast
            float e0 = embg[lane*37 + v];
            float e1 = embg[(lane+32)*37 + v];
            float hb[8] = {h0.x,h0.y,h0.z,h0.w,h1.x,h1.y,h1.z,h1.w};
            #pragma unroll
            for (int i = 0; i < 8; i++) {
                s0[i] = fmaf(hb[i], e0, s0[i]);
                s1[i] = fmaf(hb[i], e1, s1[i]);
            }
        }

        // exp + per-lane running denom/argmax (reduced once at the end)
        #pragma unroll
        for (int i = 0; i < 8; i++) {
            float a = s0[i], b = s1[i];
            if (a > mx[i]) { mx[i] = a; mi[i] = kb + lane; }
            if (b > mx[i]) { mx[i] = b; mi[i] = kb + lane + 32; }
            float e0 = __expf(2.f*a), e1 = __expf(2.f*b);
            es[i] += e0 + e1;
            Pw[i*68 + lane]      = e0;
            Pw[i*68 + lane + 32] = e1;
        }
        __syncwarp();

        // GEMM2: hv[t] += sum_k P[t][k]*emb[k][lane]  (ev conflict-free, P broadcast)
        #pragma unroll 2
        for (int kk = 0; kk < 64; kk += 4) {
            float ev0 = embg[(kk+0)*37 + lane];
            float ev1 = embg[(kk+1)*37 + lane];
            float ev2 = embg[(kk+2)*37 + lane];
            float ev3 = embg[(kk+3)*37 + lane];
            #pragma unroll
            for (int i = 0; i < 8; i++) {
                float4 p = *(const float4*)&Pw[i*68 + kk];    // broadcast
                hv[i] = fmaf(p.x,ev0, fmaf(p.y,ev1, fmaf(p.z,ev2, fmaf(p.w,ev3, hv[i]))));
            }
        }
        __syncwarp();
    }

    // per-warp butterflies (registers only)
    #pragma unroll
    for (int i = 0; i < 8; i++) {
        float e = es[i]; float mm = mx[i]; int ii = mi[i];
        #pragma unroll
        for (int o = 16; o; o >>= 1) {
            e += __shfl_xor_sync(0xffffffffu, e, o);
            float om = __shfl_xor_sync(0xffffffffu, mm, o);
            int   oi = __shfl_xor_sync(0xffffffffu, ii, o);
            if (om > mm || (om == mm && oi < ii)) { mm = om; ii = oi; }
        }
        es[i] = e; mx[i] = mm; mi[i] = ii;
    }
    __syncthreads();            // everyone done with embk/Ps
    if (lane == 0) {
        #pragma unroll
        for (int i = 0; i < 8; i++) { denomW[wid][i]=es[i]; maxW[wid][i]=mx[i]; idxW[wid][i]=mi[i]; }
    }
    #pragma unroll
    for (int i = 0; i < 8; i++)
        hvqP[(g*32 + t0 + i)*33 + lane] = hv[i];
    __syncthreads();

    // merge groups: denom, argmax, code output
    if (tx < 32) {
        int t = tx, wA = t >> 3, i = t & 7;
        denom_s[t] = denomW[wA][i] + denomW[wA+4][i];
        float mA = maxW[wA][i]; int iA = idxW[wA][i];
        float mB = maxW[wA+4][i]; int iB = idxW[wA+4][i];
        int code = (mB > mA || (mB == mA && iB < iA)) ? iB : iA;
        bool on = (attn_mask[t_base + t] == 1.0f);
        mask_s[t] = on ? 1.0f : 0.0f;
        if (out_size >= QSZ + BLn) out[QSZ + t_base + t] = on ? (float)code : 0.0f;
    }
    __syncthreads();
    #pragma unroll
    for (int it = 0; it < 4; it++) {   // hvq = (P0+P1)/denom * mask  -> Ps region
        int i = tx + it*256;
        int t = i >> 5, v = i & 31;
        hvq[t*33 + v] = (hvqP[t*33 + v] + hvqP[(t+32)*33 + v]) * mask_s[t] / denom_s[t];
    }
    __syncthreads();

    // ================= Phase C: projection out = hvq @ Wpi^T + bpi ==========
    if (out_size >= QSZ) {
        float4 bp4 = ((const float4*)bpi)[tx];          // d = tx*4
        for (int tg = 0; tg < 4; tg++) {
            float4 a[8];
            #pragma unroll
            for (int i = 0; i < 8; i++) a[i] = bp4;
            #pragma unroll 4
            for (int v = 0; v < 32; v++) {
                float4 w4 = *(const float4*)(g_wpit + v*Dn + tx*4);  // coalesced, L1/L2
                #pragma unroll
                for (int i = 0; i < 8; i++) {
                    float b = hvq[(tg*8 + i)*33 + v];                // broadcast
                    a[i].x = fmaf(b, w4.x, a[i].x);
                    a[i].y = fmaf(b, w4.y, a[i].y);
                    a[i].z = fmaf(b, w4.z, a[i].z);
                    a[i].w = fmaf(b, w4.w, a[i].w);
                }
            }
            #pragma unroll
            for (int i = 0; i < 8; i++)
                *(float4*)(out + (size_t)(t_base + tg*8 + i)*Dn + tx*4) = a[i];
        }
    }
}

extern "C" void kernel_launch(void* const* d_in, const int* in_sizes, int n_in,
                              void* d_out, int out_size) {
    const float* h         = (const float*)d_in[0];
    const float* attn_mask = (const float*)d_in[1];
    const float* Wp        = (const float*)d_in[2];
    const float* bp        = (const float*)d_in[3];
    const float* Wpi       = (const float*)d_in[4];
    const float* bpi       = (const float*)d_in[5];
    const float* emb       = (const float*)d_in[6];
    float* out = (float*)d_out;

    k_prep_emb<<<Kn/8, 256>>>(emb);
    k_prep_w<<<(Vn*Dn)/256, 256>>>(Wp, Wpi, out, out_size);
    k_fused<<<BLn/32, 256>>>(h, bp, attn_mask, bpi, out, out_size);
}